// round 1
// baseline (speedup 1.0000x reference)
#include <cuda_runtime.h>

// Problem constants
#define BB 32
#define TT 24
#define NN 325
#define DD 64
#define NHEAD 8
#define DHEAD 8

#define NB 4                 // nodes per CTA
#define MROWS (NB * TT)      // 96 rows per CTA tile
#define NTILES ((NN + NB - 1) / NB)   // 82
#define NTHREADS 256

// shared memory layout (floats)
#define XS_OFF 0
#define QS_OFF 6144
#define KS_OFF 12288
#define VS_OFF 18432
#define WS_OFF 24576
#define SMEM_FLOATS 28672
#define SMEM_BYTES (SMEM_FLOATS * 4)   // 114688 B per CTA -> 2 CTAs/SM

// ---------------------------------------------------------------------------
// Stage one 64x64 weight matrix into shared memory (coalesced float4).
// ---------------------------------------------------------------------------
__device__ __forceinline__ void load_weight(float* __restrict__ Wsm,
                                            const float* __restrict__ Wg,
                                            int tid) {
#pragma unroll
    for (int i = 0; i < 4; ++i) {
        int idx = (tid + i * NTHREADS) * 4;   // 1024 float4 total
        *(float4*)(Wsm + idx) = *(const float4*)(Wg + idx);
    }
}

#define FMA4(XCOMP, WREG, ACC)                       \
    ACC[0] = fmaf((XCOMP), (WREG).x, ACC[0]);        \
    ACC[1] = fmaf((XCOMP), (WREG).y, ACC[1]);        \
    ACC[2] = fmaf((XCOMP), (WREG).z, ACC[2]);        \
    ACC[3] = fmaf((XCOMP), (WREG).w, ACC[3]);

// ---------------------------------------------------------------------------
// 96x64 = [96x64] @ [64x64] GEMM, smem->smem, optional ReLU epilogue.
// Thread tile: 6 rows x 4 cols (16 row-groups x 16 col-groups = 256 threads).
// ---------------------------------------------------------------------------
template <bool RELU>
__device__ __forceinline__ void gemm_tile(const float* __restrict__ A,
                                          const float* __restrict__ Wsm,
                                          const float* __restrict__ bias,
                                          float* __restrict__ outs,
                                          int tid) {
    const int rg = tid >> 4;
    const int cg = tid & 15;
    const int r0 = rg * 6;
    const int c0 = cg * 4;
    float acc[6][4];
#pragma unroll
    for (int i = 0; i < 6; ++i)
#pragma unroll
        for (int j = 0; j < 4; ++j) acc[i][j] = 0.0f;

#pragma unroll 2
    for (int kk = 0; kk < 64; kk += 4) {
        float4 xf[6];
        float4 wf[4];
#pragma unroll
        for (int i = 0; i < 6; ++i)
            xf[i] = *(const float4*)(A + (r0 + i) * DD + kk);
#pragma unroll
        for (int j = 0; j < 4; ++j)
            wf[j] = *(const float4*)(Wsm + (kk + j) * DD + c0);
#pragma unroll
        for (int i = 0; i < 6; ++i) {
            FMA4(xf[i].x, wf[0], acc[i]);
            FMA4(xf[i].y, wf[1], acc[i]);
            FMA4(xf[i].z, wf[2], acc[i]);
            FMA4(xf[i].w, wf[3], acc[i]);
        }
    }

    float4 bb = *(const float4*)(bias + c0);
#pragma unroll
    for (int i = 0; i < 6; ++i) {
        float4 r;
        r.x = acc[i][0] + bb.x;
        r.y = acc[i][1] + bb.y;
        r.z = acc[i][2] + bb.z;
        r.w = acc[i][3] + bb.w;
        if (RELU) {
            r.x = fmaxf(r.x, 0.0f);
            r.y = fmaxf(r.y, 0.0f);
            r.z = fmaxf(r.z, 0.0f);
            r.w = fmaxf(r.w, 0.0f);
        }
        *(float4*)(outs + (r0 + i) * DD + c0) = r;
    }
}

// ---------------------------------------------------------------------------
// Final GEMM: smem -> global output, bias, no ReLU, node bound guard.
// ---------------------------------------------------------------------------
__device__ __forceinline__ void gemm_out(const float* __restrict__ A,
                                         const float* __restrict__ Wsm,
                                         const float* __restrict__ bias,
                                         float* __restrict__ Y,
                                         int b, int n0, int tid) {
    const int rg = tid >> 4;
    const int cg = tid & 15;
    const int r0 = rg * 6;
    const int c0 = cg * 4;
    float acc[6][4];
#pragma unroll
    for (int i = 0; i < 6; ++i)
#pragma unroll
        for (int j = 0; j < 4; ++j) acc[i][j] = 0.0f;

#pragma unroll 2
    for (int kk = 0; kk < 64; kk += 4) {
        float4 xf[6];
        float4 wf[4];
#pragma unroll
        for (int i = 0; i < 6; ++i)
            xf[i] = *(const float4*)(A + (r0 + i) * DD + kk);
#pragma unroll
        for (int j = 0; j < 4; ++j)
            wf[j] = *(const float4*)(Wsm + (kk + j) * DD + c0);
#pragma unroll
        for (int i = 0; i < 6; ++i) {
            FMA4(xf[i].x, wf[0], acc[i]);
            FMA4(xf[i].y, wf[1], acc[i]);
            FMA4(xf[i].z, wf[2], acc[i]);
            FMA4(xf[i].w, wf[3], acc[i]);
        }
    }

    float4 bb = *(const float4*)(bias + c0);
#pragma unroll
    for (int i = 0; i < 6; ++i) {
        int row = r0 + i;
        int node = row / TT;
        int t = row - node * TT;
        int n = n0 + node;
        if (n < NN) {
            float4 r;
            r.x = acc[i][0] + bb.x;
            r.y = acc[i][1] + bb.y;
            r.z = acc[i][2] + bb.z;
            r.w = acc[i][3] + bb.w;
            *(float4*)(Y + ((size_t)(b * TT + t) * NN + n) * DD + c0) = r;
        }
    }
}

// ---------------------------------------------------------------------------
// Per-(node, t, head) attention: 24-step masked softmax over temporal axis.
// tri = triu => keep s >= t. Masked fill -2^15+1 underflows to exact 0 after
// exp(x - max) in fp32, identical to using -1e30 here.
// ---------------------------------------------------------------------------
__device__ __forceinline__ void attention(const float* __restrict__ Qs,
                                          const float* __restrict__ Ks,
                                          const float* __restrict__ Vs,
                                          float* __restrict__ Os,
                                          int tid) {
    const float scale = 0.3535533905932738f;  // 1/sqrt(8)
#pragma unroll 1
    for (int iter = 0; iter < 3; ++iter) {
        int task = iter * NTHREADS + tid;     // 0..767
        int h = task & 7;
        int t = (task >> 3) % TT;
        int node = task / (TT * NHEAD);
        int base = node * TT;
        int hc = h * DHEAD;

        float4 q0 = *(const float4*)(Qs + (base + t) * DD + hc);
        float4 q1 = *(const float4*)(Qs + (base + t) * DD + hc + 4);
        q0.x *= scale; q0.y *= scale; q0.z *= scale; q0.w *= scale;
        q1.x *= scale; q1.y *= scale; q1.z *= scale; q1.w *= scale;

        float p[TT];
        float m = -1e30f;
#pragma unroll
        for (int s = 0; s < TT; ++s) {
            float4 k0 = *(const float4*)(Ks + (base + s) * DD + hc);
            float4 k1 = *(const float4*)(Ks + (base + s) * DD + hc + 4);
            float dot = q0.x * k0.x;
            dot = fmaf(q0.y, k0.y, dot);
            dot = fmaf(q0.z, k0.z, dot);
            dot = fmaf(q0.w, k0.w, dot);
            dot = fmaf(q1.x, k1.x, dot);
            dot = fmaf(q1.y, k1.y, dot);
            dot = fmaf(q1.z, k1.z, dot);
            dot = fmaf(q1.w, k1.w, dot);
            dot = (s >= t) ? dot : -1e30f;
            p[s] = dot;
            m = fmaxf(m, dot);
        }
        float sum = 0.0f;
#pragma unroll
        for (int s = 0; s < TT; ++s) {
            float e = __expf(p[s] - m);   // masked -> exp(-1e30) == 0 exactly
            p[s] = e;
            sum += e;
        }
        float inv = 1.0f / sum;

        float o[8] = {0, 0, 0, 0, 0, 0, 0, 0};
#pragma unroll
        for (int s = 0; s < TT; ++s) {
            float4 v0 = *(const float4*)(Vs + (base + s) * DD + hc);
            float4 v1 = *(const float4*)(Vs + (base + s) * DD + hc + 4);
            o[0] = fmaf(p[s], v0.x, o[0]);
            o[1] = fmaf(p[s], v0.y, o[1]);
            o[2] = fmaf(p[s], v0.z, o[2]);
            o[3] = fmaf(p[s], v0.w, o[3]);
            o[4] = fmaf(p[s], v1.x, o[4]);
            o[5] = fmaf(p[s], v1.y, o[5]);
            o[6] = fmaf(p[s], v1.z, o[6]);
            o[7] = fmaf(p[s], v1.w, o[7]);
        }
        float4 r0 = make_float4(o[0] * inv, o[1] * inv, o[2] * inv, o[3] * inv);
        float4 r1 = make_float4(o[4] * inv, o[5] * inv, o[6] * inv, o[7] * inv);
        *(float4*)(Os + (base + t) * DD + hc) = r0;
        *(float4*)(Os + (base + t) * DD + hc + 4) = r1;
    }
}

// ---------------------------------------------------------------------------
// Fused kernel: one CTA per (batch, 4-node tile).
// ---------------------------------------------------------------------------
__global__ void __launch_bounds__(NTHREADS, 2)
temporal_attention_fused(const float* __restrict__ X,
                         const float* __restrict__ Wq, const float* __restrict__ bq,
                         const float* __restrict__ Wk, const float* __restrict__ bk,
                         const float* __restrict__ Wv, const float* __restrict__ bv,
                         const float* __restrict__ Wf1, const float* __restrict__ bf1,
                         const float* __restrict__ Wf2, const float* __restrict__ bf2,
                         float* __restrict__ Y) {
    extern __shared__ float smem[];
    float* Xs = smem + XS_OFF;   // also reused for attention output
    float* Qs = smem + QS_OFF;   // also reused for FC1 hidden
    float* Ks = smem + KS_OFF;
    float* Vs = smem + VS_OFF;
    float* Ws = smem + WS_OFF;

    const int tid = threadIdx.x;
    const int n0 = blockIdx.x * NB;
    const int b = blockIdx.y;

    // Load X tile: rows = node*24 + t, zero-fill out-of-range nodes.
#pragma unroll 2
    for (int i = tid; i < MROWS * 16; i += NTHREADS) {
        int row = i >> 4;
        int f4 = i & 15;
        int node = row / TT;
        int t = row - node * TT;
        int n = n0 + node;
        float4 v = make_float4(0.f, 0.f, 0.f, 0.f);
        if (n < NN)
            v = *(const float4*)(X + ((size_t)(b * TT + t) * NN + n) * DD + f4 * 4);
        *(float4*)(Xs + row * DD + f4 * 4) = v;
    }
    load_weight(Ws, Wq, tid);
    __syncthreads();

    gemm_tile<true>(Xs, Ws, bq, Qs, tid);      // q = relu(X@Wq + bq)
    __syncthreads();
    load_weight(Ws, Wk, tid);
    __syncthreads();
    gemm_tile<true>(Xs, Ws, bk, Ks, tid);      // k
    __syncthreads();
    load_weight(Ws, Wv, tid);
    __syncthreads();
    gemm_tile<true>(Xs, Ws, bv, Vs, tid);      // v
    __syncthreads();

    // Attention (writes into Xs) while also staging Wf1 (Ws is free).
    load_weight(Ws, Wf1, tid);
    attention(Qs, Ks, Vs, Xs, tid);
    __syncthreads();

    gemm_tile<true>(Xs, Ws, bf1, Qs, tid);     // h = relu(out@Wf1 + bf1) -> Qs
    __syncthreads();
    load_weight(Ws, Wf2, tid);
    __syncthreads();
    gemm_out(Qs, Ws, bf2, Y, b, n0, tid);      // y = h@Wf2 + bf2 -> global
}

// ---------------------------------------------------------------------------
// kernel_launch: inputs per metadata order:
// 0=X 1=STE(unused) 2=Wq 3=bq 4=Wk 5=bk 6=Wv 7=bv 8=Wf1 9=bf1 10=Wf2 11=bf2
// 12=K 13=d 14=bn_decay (scalars, hardcoded)
// ---------------------------------------------------------------------------
extern "C" void kernel_launch(void* const* d_in, const int* in_sizes, int n_in,
                              void* d_out, int out_size) {
    const float* X   = (const float*)d_in[0];
    const float* Wq  = (const float*)d_in[2];
    const float* bq  = (const float*)d_in[3];
    const float* Wk  = (const float*)d_in[4];
    const float* bk  = (const float*)d_in[5];
    const float* Wv  = (const float*)d_in[6];
    const float* bv  = (const float*)d_in[7];
    const float* Wf1 = (const float*)d_in[8];
    const float* bf1 = (const float*)d_in[9];
    const float* Wf2 = (const float*)d_in[10];
    const float* bf2 = (const float*)d_in[11];
    float* Y = (float*)d_out;

    cudaFuncSetAttribute(temporal_attention_fused,
                         cudaFuncAttributeMaxDynamicSharedMemorySize, SMEM_BYTES);

    dim3 grid(NTILES, BB);
    temporal_attention_fused<<<grid, NTHREADS, SMEM_BYTES>>>(
        X, Wq, bq, Wk, bk, Wv, bv, Wf1, bf1, Wf2, bf2, Y);
}